// round 13
// baseline (speedup 1.0000x reference)
#include <cuda_runtime.h>
#include <cstdint>

// Shapes fixed by the problem: x (64,64,128,128) fp32, coeff (64,32) fp32, out (64,64) fp32.
#define N_ELEM   67108864   // 64*64*128*128
#define N_F4     16777216   // N_ELEM/4
#define N_PLANES 4096       // N*C
#define HW4      4096       // 128*128/4
#define BINS     32
#define MM_GRID  1184       // 148 SMs * 8 blocks: exactly one full wave
#define MARGIN   2.0e-4f    // bin-fraction safety margin (true error < ~3e-5)

// per-block min/max partials (written fresh every launch -> no init kernel, no atomics)
__device__ float2 g_partials[MM_GRID];

__global__ void __launch_bounds__(256) minmax_kernel(const float4* __restrict__ x) {
    float lo =  3.402823466e38f;
    float hi = -3.402823466e38f;
    const int base   = blockIdx.x * 256 + threadIdx.x;
    const int stride = MM_GRID * 256;
    #pragma unroll 8
    for (int i = base; i < N_F4; i += stride) {
        float4 v = x[i];
        lo = fminf(lo, fminf(fminf(v.x, v.y), fminf(v.z, v.w)));
        hi = fmaxf(hi, fmaxf(fmaxf(v.x, v.y), fmaxf(v.z, v.w)));
    }
    #pragma unroll
    for (int o = 16; o; o >>= 1) {
        lo = fminf(lo, __shfl_xor_sync(0xFFFFFFFFu, lo, o));
        hi = fmaxf(hi, __shfl_xor_sync(0xFFFFFFFFu, hi, o));
    }
    __shared__ float s_lo[8], s_hi[8];
    const int t = threadIdx.x;
    if ((t & 31) == 0) { s_lo[t >> 5] = lo; s_hi[t >> 5] = hi; }
    __syncthreads();
    if (t < 32) {
        lo = (t < 8) ? s_lo[t] :  3.402823466e38f;
        hi = (t < 8) ? s_hi[t] : -3.402823466e38f;
        #pragma unroll
        for (int o = 4; o; o >>= 1) {
            lo = fminf(lo, __shfl_xor_sync(0xFFFFFFFFu, lo, o));
            hi = fmaxf(hi, __shfl_xor_sync(0xFFFFFFFFu, hi, o));
        }
        if (t == 0) g_partials[blockIdx.x] = make_float2(lo, hi);
    }
}

// Exact searchsorted-right fix-up: valid for ALL inputs (not just near-boundary).
// tau[ir] computed with exact jnp.linspace fp32 arithmetic.
__device__ __forceinline__ int fix_bin(float xv, float f, float xmin, float delta) {
    const int   ir    = (int)rintf(f);
    const float tau_r = __fadd_rn(xmin, __fmul_rn((float)ir, delta));
    int i = (xv >= tau_r) ? ir : ir - 1;
    return min(max(i, 0), BINS - 1);
}

__global__ void __launch_bounds__(256) hpool_kernel(const float4* __restrict__ x,
                                                    const float* __restrict__ coeff,
                                                    float* __restrict__ out) {
    __shared__ float s_red[8];
    __shared__ float s_mm[2];

    const int t = threadIdx.x;

    // ---- prologue: reduce per-block minmax partials (deterministic, L2-resident) ----
    {
        float lo =  3.402823466e38f;
        float hi = -3.402823466e38f;
        #pragma unroll
        for (int i = t; i < MM_GRID; i += 256) {
            float2 p = g_partials[i];
            lo = fminf(lo, p.x);
            hi = fmaxf(hi, p.y);
        }
        #pragma unroll
        for (int o = 16; o; o >>= 1) {
            lo = fminf(lo, __shfl_xor_sync(0xFFFFFFFFu, lo, o));
            hi = fmaxf(hi, __shfl_xor_sync(0xFFFFFFFFu, hi, o));
        }
        if ((t & 31) == 0) { s_red[(t >> 5)] = lo; }
        __syncthreads();
        if (t < 32) {
            float a = (t < 8) ? s_red[t] : 3.402823466e38f;
            #pragma unroll
            for (int o = 4; o; o >>= 1) a = fminf(a, __shfl_xor_sync(0xFFFFFFFFu, a, o));
            if (t == 0) s_mm[0] = a;
        }
        __syncthreads();
        if ((t & 31) == 0) { s_red[(t >> 5)] = hi; }
        __syncthreads();
        if (t < 32) {
            float a = (t < 8) ? s_red[t] : -3.402823466e38f;
            #pragma unroll
            for (int o = 4; o; o >>= 1) a = fmaxf(a, __shfl_xor_sync(0xFFFFFFFFu, a, o));
            if (t == 0) s_mm[1] = a;
        }
        __syncthreads();
    }

    const float xmin = s_mm[0];
    const float xmax = s_mm[1];
    // jnp.linspace fp32 semantics: delta=(stop-start)/32; tau[i]=rn(start + rn(i*delta))
    const float delta     = __fdiv_rn(__fsub_rn(xmax, xmin), 32.0f);
    const float inv_delta = __frcp_rn(delta);
    const float nbase     = -xmin * inv_delta;

    // Reverse plane order: minmax streamed forward, its tail is L2-resident
    // (and this leaves the FRONT of x in L2 for the next graph replay's minmax).
    const int plane = (N_PLANES - 1) - (int)blockIdx.x;
    const int c = plane & 63;

    // lane l holds coeff[c][l]; gather via shfl (BINS == warp size)
    const float cf_lane = coeff[c * BINS + (t & 31)];

    const float4* __restrict__ p = x + (size_t)plane * HW4;
    float acc0 = 0.0f, acc1 = 0.0f;

    #pragma unroll 4
    for (int it = 0; it < 16; it++) {
        const float4 v = p[it * 256 + t];

        // bin fractions (error < ~3e-5 bins)
        const float f0 = fmaf(v.x, inv_delta, nbase);
        const float f1 = fmaf(v.y, inv_delta, nbase);
        const float f2 = fmaf(v.z, inv_delta, nbase);
        const float f3 = fmaf(v.w, inv_delta, nbase);

        // fast-path indices: trunc (clamps tiny negatives to 0; f>=32 only near
        // a boundary, where the fixup below clamps)
        int i0 = (int)f0, i1 = (int)f1, i2 = (int)f2, i3 = (int)f3;

        // ONE boundary check per float4: distance of each f to nearest integer
        const float d0 = fabsf(f0 - rintf(f0));
        const float d1 = fabsf(f1 - rintf(f1));
        const float d2 = fabsf(f2 - rintf(f2));
        const float d3 = fabsf(f3 - rintf(f3));
        if (fminf(fminf(d0, d1), fminf(d2, d3)) < MARGIN) {
            // rare (~1.2% of elements-windows): recompute all 4 exactly
            // (fix_bin is valid for every lane, so no per-lane predicate needed)
            i0 = fix_bin(v.x, f0, xmin, delta);
            i1 = fix_bin(v.y, f1, xmin, delta);
            i2 = fix_bin(v.z, f2, xmin, delta);
            i3 = fix_bin(v.w, f3, xmin, delta);
        }

        float t0, t1, t2, t3;
        asm("tanh.approx.f32 %0, %1;" : "=f"(t0) : "f"(v.x));
        asm("tanh.approx.f32 %0, %1;" : "=f"(t1) : "f"(v.y));
        asm("tanh.approx.f32 %0, %1;" : "=f"(t2) : "f"(v.z));
        asm("tanh.approx.f32 %0, %1;" : "=f"(t3) : "f"(v.w));

        const float c0 = __shfl_sync(0xFFFFFFFFu, cf_lane, i0);
        const float c1 = __shfl_sync(0xFFFFFFFFu, cf_lane, i1);
        const float c2 = __shfl_sync(0xFFFFFFFFu, cf_lane, i2);
        const float c3 = __shfl_sync(0xFFFFFFFFu, cf_lane, i3);

        acc0 = fmaf(t0, c0, acc0);
        acc1 = fmaf(t1, c1, acc1);
        acc0 = fmaf(t2, c2, acc0);
        acc1 = fmaf(t3, c3, acc1);
    }
    float acc = acc0 + acc1;

    // block reduce (8 warps)
    #pragma unroll
    for (int o = 16; o; o >>= 1) acc += __shfl_xor_sync(0xFFFFFFFFu, acc, o);
    __syncthreads();  // s_red reuse
    if ((t & 31) == 0) s_red[t >> 5] = acc;
    __syncthreads();
    if (t < 32) {
        float a = (t < 8) ? s_red[t] : 0.0f;
        #pragma unroll
        for (int o = 4; o; o >>= 1) a += __shfl_xor_sync(0xFFFFFFFFu, a, o);
        if (t == 0) out[plane] = a;
    }
}

extern "C" void kernel_launch(void* const* d_in, const int* in_sizes, int n_in,
                              void* d_out, int out_size) {
    const float4* x     = (const float4*)d_in[0];
    const float*  coeff = (const float*)d_in[1];
    float*        out   = (float*)d_out;

    minmax_kernel<<<MM_GRID, 256>>>(x);
    hpool_kernel<<<N_PLANES, 256>>>(x, coeff, out);
}

// round 15
// speedup vs baseline: 1.1409x; 1.1409x over previous
#include <cuda_runtime.h>
#include <cstdint>

// Shapes fixed by the problem: x (64,64,128,128) fp32, coeff (64,32) fp32, out (64,64) fp32.
#define N_ELEM   67108864   // 64*64*128*128
#define N_F4     16777216   // N_ELEM/4
#define N_PLANES 4096       // N*C
#define HW4      4096       // 128*128/4
#define BINS     32
#define MM_GRID  1184       // 148 SMs * 8 blocks: exactly one full wave
#define MAGIC    12582912.0f            // 2^23 + 2^22: ulp=1 -> FADD rounds to nearest int
#define MAGIC_I  0x4B400000             // __float_as_int(MAGIC)

// per-block min/max partials (written fresh every launch -> no init kernel, no atomics)
__device__ float2 g_partials[MM_GRID];

__global__ void __launch_bounds__(256) minmax_kernel(const float4* __restrict__ x) {
    float lo =  3.402823466e38f;
    float hi = -3.402823466e38f;
    const int base   = blockIdx.x * 256 + threadIdx.x;
    const int stride = MM_GRID * 256;
    #pragma unroll 8
    for (int i = base; i < N_F4; i += stride) {
        float4 v = x[i];
        lo = fminf(lo, fminf(fminf(v.x, v.y), fminf(v.z, v.w)));
        hi = fmaxf(hi, fmaxf(fmaxf(v.x, v.y), fmaxf(v.z, v.w)));
    }
    #pragma unroll
    for (int o = 16; o; o >>= 1) {
        lo = fminf(lo, __shfl_xor_sync(0xFFFFFFFFu, lo, o));
        hi = fmaxf(hi, __shfl_xor_sync(0xFFFFFFFFu, hi, o));
    }
    __shared__ float s_lo[8], s_hi[8];
    const int t = threadIdx.x;
    if ((t & 31) == 0) { s_lo[t >> 5] = lo; s_hi[t >> 5] = hi; }
    __syncthreads();
    if (t < 32) {
        lo = (t < 8) ? s_lo[t] :  3.402823466e38f;
        hi = (t < 8) ? s_hi[t] : -3.402823466e38f;
        #pragma unroll
        for (int o = 4; o; o >>= 1) {
            lo = fminf(lo, __shfl_xor_sync(0xFFFFFFFFu, lo, o));
            hi = fmaxf(hi, __shfl_xor_sync(0xFFFFFFFFu, hi, o));
        }
        if (t == 0) g_partials[blockIdx.x] = make_float2(lo, hi);
    }
}

// Branchless EXACT searchsorted-right bin index, valid for every x in [xmin, xmax].
// rint(f) via the 2^23+2^22 magic (applied to f by FADD, never folded into an FFMA
// addend -- MAGIC's ulp=1 would quantize any merged constant). True bin k obeys
// rint(f) in {k, k+1}; comparing x against the exactly-computed tau[rint(f)]
// (jnp.linspace fp32 arithmetic: rn(xmin + rn(i*delta))) resolves it exactly.
__device__ __forceinline__ int bin_exact(float xv, float inv_delta, float nbase,
                                         float xmin, float delta) {
    const float f   = fmaf(xv, inv_delta, nbase);
    const float m2  = __fadd_rn(f, MAGIC);            // integer-grid rounding
    const float rf  = __fadd_rn(m2, -MAGIC);          // rint(f) as float (exact)
    const int   ir  = __float_as_int(m2) - MAGIC_I;   // rint(f) as int   (exact)
    const float tau = __fadd_rn(xmin, __fmul_rn(rf, delta));
    int i = (xv >= tau) ? ir : ir - 1;                // i >= 0 always (x >= xmin = tau[0])
    return min(i, BINS - 1);
}

__global__ void __launch_bounds__(256) hpool_kernel(const float4* __restrict__ x,
                                                    const float* __restrict__ coeff,
                                                    float* __restrict__ out) {
    __shared__ float s_red[8];
    __shared__ float s_mm[2];

    const int t = threadIdx.x;

    // ---- prologue: reduce per-block minmax partials (deterministic, L2-resident) ----
    {
        float lo =  3.402823466e38f;
        float hi = -3.402823466e38f;
        #pragma unroll
        for (int i = t; i < MM_GRID; i += 256) {
            float2 p = g_partials[i];
            lo = fminf(lo, p.x);
            hi = fmaxf(hi, p.y);
        }
        #pragma unroll
        for (int o = 16; o; o >>= 1) {
            lo = fminf(lo, __shfl_xor_sync(0xFFFFFFFFu, lo, o));
            hi = fmaxf(hi, __shfl_xor_sync(0xFFFFFFFFu, hi, o));
        }
        if ((t & 31) == 0) { s_red[(t >> 5)] = lo; }
        __syncthreads();
        if (t < 32) {
            float a = (t < 8) ? s_red[t] : 3.402823466e38f;
            #pragma unroll
            for (int o = 4; o; o >>= 1) a = fminf(a, __shfl_xor_sync(0xFFFFFFFFu, a, o));
            if (t == 0) s_mm[0] = a;
        }
        __syncthreads();
        if ((t & 31) == 0) { s_red[(t >> 5)] = hi; }
        __syncthreads();
        if (t < 32) {
            float a = (t < 8) ? s_red[t] : -3.402823466e38f;
            #pragma unroll
            for (int o = 4; o; o >>= 1) a = fmaxf(a, __shfl_xor_sync(0xFFFFFFFFu, a, o));
            if (t == 0) s_mm[1] = a;
        }
        __syncthreads();
    }

    const float xmin = s_mm[0];
    const float xmax = s_mm[1];
    // jnp.linspace fp32 semantics: delta=(stop-start)/32; tau[i]=rn(start + rn(i*delta))
    const float delta     = __fdiv_rn(__fsub_rn(xmax, xmin), 32.0f);
    const float inv_delta = __frcp_rn(delta);
    const float nbase     = -xmin * inv_delta;

    // Reverse plane order: minmax streamed forward, its tail is L2-resident
    // (and this leaves the FRONT of x in L2 for the next graph replay's minmax).
    const int plane = (N_PLANES - 1) - (int)blockIdx.x;
    const int c = plane & 63;

    // lane l holds coeff[c][l]; gather via shfl (BINS == warp size)
    const float cf_lane = coeff[c * BINS + (t & 31)];

    const float4* __restrict__ p = x + (size_t)plane * HW4;
    float acc0 = 0.0f, acc1 = 0.0f;

    #pragma unroll 4
    for (int it = 0; it < 16; it++) {
        const float4 v = p[it * 256 + t];

        const int i0 = bin_exact(v.x, inv_delta, nbase, xmin, delta);
        const int i1 = bin_exact(v.y, inv_delta, nbase, xmin, delta);
        const int i2 = bin_exact(v.z, inv_delta, nbase, xmin, delta);
        const int i3 = bin_exact(v.w, inv_delta, nbase, xmin, delta);

        float t0, t1, t2, t3;
        asm("tanh.approx.f32 %0, %1;" : "=f"(t0) : "f"(v.x));
        asm("tanh.approx.f32 %0, %1;" : "=f"(t1) : "f"(v.y));
        asm("tanh.approx.f32 %0, %1;" : "=f"(t2) : "f"(v.z));
        asm("tanh.approx.f32 %0, %1;" : "=f"(t3) : "f"(v.w));

        const float c0 = __shfl_sync(0xFFFFFFFFu, cf_lane, i0);
        const float c1 = __shfl_sync(0xFFFFFFFFu, cf_lane, i1);
        const float c2 = __shfl_sync(0xFFFFFFFFu, cf_lane, i2);
        const float c3 = __shfl_sync(0xFFFFFFFFu, cf_lane, i3);

        acc0 = fmaf(t0, c0, acc0);
        acc1 = fmaf(t1, c1, acc1);
        acc0 = fmaf(t2, c2, acc0);
        acc1 = fmaf(t3, c3, acc1);
    }
    float acc = acc0 + acc1;

    // block reduce (8 warps)
    #pragma unroll
    for (int o = 16; o; o >>= 1) acc += __shfl_xor_sync(0xFFFFFFFFu, acc, o);
    __syncthreads();  // s_red reuse
    if ((t & 31) == 0) s_red[t >> 5] = acc;
    __syncthreads();
    if (t < 32) {
        float a = (t < 8) ? s_red[t] : 0.0f;
        #pragma unroll
        for (int o = 4; o; o >>= 1) a += __shfl_xor_sync(0xFFFFFFFFu, a, o);
        if (t == 0) out[plane] = a;
    }
}

extern "C" void kernel_launch(void* const* d_in, const int* in_sizes, int n_in,
                              void* d_out, int out_size) {
    const float4* x     = (const float4*)d_in[0];
    const float*  coeff = (const float*)d_in[1];
    float*        out   = (float*)d_out;

    minmax_kernel<<<MM_GRID, 256>>>(x);
    hpool_kernel<<<N_PLANES, 256>>>(x, coeff, out);
}